// round 1
// baseline (speedup 1.0000x reference)
#include <cuda_runtime.h>
#include <cstdint>
#include <math.h>

#define BB  8
#define LL  2048
#define DDIM 512
#define MMH 8
#define DH  64
#define KH  256
#define NBM (BB*MMH)     // 64

// ---------------- scratch (static __device__ globals; no allocation) ----------
__device__ float g_hyp[BB*LL*DDIM];                 // x + PE
__device__ float g_W1 [NBM*LL*KH];                  // [bm][l][k]
__device__ float g_W2 [NBM*LL*KH];
__device__ float g_P  [NBM*DH*KH];                  // gelu(xt @ W1) [bm][d][k]
__device__ float g_pre[BB*LL*DDIM];                 // pre-LN mix
__device__ float g_mix[BB*LL*DDIM];
__device__ float g_c1 [BB*LL*DDIM];                 // LN(mix) w/ conv_ln1
__device__ float g_y  [BB*LL*2*DDIM];               // bneck out
__device__ float g_glu[BB*LL*DDIM];
__device__ float g_cv [BB*LL*DDIM];                 // depthwise conv out
__device__ float g_c2 [BB*LL*DDIM];                 // gelu(LN(conv))

__device__ __forceinline__ float gelu_f(float v){
    return 0.5f*v*(1.0f + erff(v*0.70710678118654752f));
}

// ---------------- kernel 0: hyp = x + sinusoidal PE -------------------------
__global__ void k_hyp(const float* __restrict__ x){
    int idx = blockIdx.x*blockDim.x + threadIdx.x;
    if (idx >= BB*LL*DDIM) return;
    int d = idx & (DDIM-1);
    int l = (idx >> 9) & (LL-1);
    int j2 = d & ~1;  // 2*(d/2)
    float den = expf((float)j2 * (-9.210340371976184f/(float)DDIM));
    float ang = (float)l * den;
    float pe = (d & 1) ? cosf(ang) : sinf(ang);
    g_hyp[idx] = x[idx] + pe;
}

// ---------------- kernel 1: per-head hyper-MLP (produces W1 or W2) ----------
// grid: (L/64, M, B*2).  which = blockIdx.z&1 selects w1-set / w2-set.
// smem floats: fc1s 4096 | fc2t 64*257 | b1s 64 | b2s 256 | Xs 64*65 | Ht 64*65
#define PMLP_SMEM_FLOATS (4096 + 64*257 + 64 + 256 + 64*65 + 64*65)
__global__ void k_pmlp(const float* __restrict__ f1w_a, const float* __restrict__ f1b_a,
                       const float* __restrict__ f2w_a, const float* __restrict__ f2b_a,
                       const float* __restrict__ f1w_b, const float* __restrict__ f1b_b,
                       const float* __restrict__ f2w_b, const float* __restrict__ f2b_b){
    extern __shared__ float sm[];
    float* fc1s = sm;                 // [h][f] 64x64
    float* fc2t = fc1s + 4096;        // [f][k] 64x257 (pad)
    float* b1s  = fc2t + 64*257;      // 64
    float* b2s  = b1s + 64;           // 256
    float* Xs   = b2s + 256;          // [l][f] 64x65
    float* Ht   = Xs  + 64*65;        // [h][l] 64x65

    int tid = threadIdx.x;
    int l0 = blockIdx.x*64, m = blockIdx.y;
    int b = blockIdx.z >> 1, which = blockIdx.z & 1;
    const float* f1w = which ? f1w_b : f1w_a;
    const float* f1b = which ? f1b_b : f1b_a;
    const float* f2w = which ? f2w_b : f2w_a;
    const float* f2b = which ? f2b_b : f2b_a;

    for (int i = tid; i < 4096; i += 256) fc1s[i] = f1w[m*4096 + i];
    for (int i = tid; i < 16384; i += 256){
        int k = i >> 6, f = i & 63;
        fc2t[f*257 + k] = f2w[m*16384 + i];
    }
    if (tid < 64)  b1s[tid] = f1b[m*64 + tid];
    b2s[tid] = f2b[m*256 + tid];
    for (int i = tid; i < 4096; i += 256){
        int l = i >> 6, f = i & 63;
        Xs[l*65 + f] = g_hyp[(size_t)(b*LL + l0 + l)*DDIM + m*64 + f];
    }
    __syncthreads();

    // stage 1: Ht[h][l] = gelu(sum_f Xs[l][f]*fc1s[h][f] + b1[h])
    {
        int lq = tid & 15, hq = tid >> 4;
        float acc[4][4] = {};
        for (int f = 0; f < 64; ++f){
            float xv[4], wv[4];
            #pragma unroll
            for (int j = 0; j < 4; ++j) xv[j] = Xs[(lq + 16*j)*65 + f];
            #pragma unroll
            for (int i = 0; i < 4; ++i) wv[i] = fc1s[(hq + 16*i)*64 + f];
            #pragma unroll
            for (int i = 0; i < 4; ++i)
                #pragma unroll
                for (int j = 0; j < 4; ++j) acc[i][j] += wv[i]*xv[j];
        }
        #pragma unroll
        for (int i = 0; i < 4; ++i){
            float bb = b1s[hq + 16*i];
            #pragma unroll
            for (int j = 0; j < 4; ++j)
                Ht[(hq + 16*i)*65 + (lq + 16*j)] = gelu_f(acc[i][j] + bb);
        }
    }
    __syncthreads();

    // stage 2: OUT[l][k] = sum_h Ht[h][l]*fc2t[h][k] + b2[k]
    {
        int kq = tid & 31, lq = tid >> 5;   // k = kq+32j (8), l = lq*8+i (8)
        float acc[8][8] = {};
        for (int h = 0; h < 64; ++h){
            float lv[8], kv[8];
            #pragma unroll
            for (int i = 0; i < 8; ++i) lv[i] = Ht[h*65 + lq*8 + i];
            #pragma unroll
            for (int j = 0; j < 8; ++j) kv[j] = fc2t[h*257 + kq + 32*j];
            #pragma unroll
            for (int i = 0; i < 8; ++i)
                #pragma unroll
                for (int j = 0; j < 8; ++j) acc[i][j] += lv[i]*kv[j];
        }
        float* Wout = which ? g_W2 : g_W1;
        int bm = b*MMH + m;
        #pragma unroll
        for (int i = 0; i < 8; ++i){
            size_t rowbase = ((size_t)bm*LL + (l0 + lq*8 + i))*KH;
            #pragma unroll
            for (int j = 0; j < 8; ++j)
                Wout[rowbase + kq + 32*j] = acc[i][j] + b2s[kq + 32*j];
        }
    }
}

// ---------------- kernel 2: P[bm][d][k] = gelu(sum_l x^T * W1) ----------------
// grid (KH/128=2, NBM=64), 256 thr, tile 64d x 128k, reduce L in 32-chunks
__global__ void k_gemmA(const float* __restrict__ x){
    __shared__ float Xs[32*65];    // [l][d]
    __shared__ float Ws[32*129];   // [l][k]
    int tid = threadIdx.x;
    int k0 = blockIdx.x*128;
    int bm = blockIdx.y, b = bm >> 3, m = bm & 7;
    int kq = tid & 31, dq = tid >> 5;  // d = dq*8+i (8), k = kq+32j (4)
    float acc[8][4] = {};
    for (int lc = 0; lc < 64; ++lc){
        int lb = lc*32;
        for (int i = tid; i < 2048; i += 256){
            int l = i >> 6, dd = i & 63;
            Xs[l*65 + dd] = x[(size_t)(b*LL + lb + l)*DDIM + m*64 + dd];
        }
        for (int i = tid; i < 4096; i += 256){
            int l = i >> 7, kk = i & 127;
            Ws[l*129 + kk] = g_W1[((size_t)bm*LL + lb + l)*KH + k0 + kk];
        }
        __syncthreads();
        #pragma unroll 4
        for (int l = 0; l < 32; ++l){
            float a8[8], w4[4];
            #pragma unroll
            for (int i = 0; i < 8; ++i) a8[i] = Xs[l*65 + dq*8 + i];
            #pragma unroll
            for (int j = 0; j < 4; ++j) w4[j] = Ws[l*129 + kq + 32*j];
            #pragma unroll
            for (int i = 0; i < 8; ++i)
                #pragma unroll
                for (int j = 0; j < 4; ++j) acc[i][j] += a8[i]*w4[j];
        }
        __syncthreads();
    }
    #pragma unroll
    for (int i = 0; i < 8; ++i){
        size_t base = ((size_t)bm*DH + dq*8 + i)*KH + k0;
        #pragma unroll
        for (int j = 0; j < 4; ++j)
            g_P[base + kq + 32*j] = gelu_f(acc[i][j]);
    }
}

// ---------------- kernel 3: pre[b][l][m*64+d] = sum_k P*W2 -------------------
// grid (L/128=16, NBM=64), 256 thr, tile 64d x 128l, reduce K=256 in 32-chunks
__global__ void k_gemmB(){
    __shared__ float Pt[32*65];    // [k][d]
    __shared__ float Wt[32*129];   // [k][l]
    int tid = threadIdx.x;
    int l0 = blockIdx.x*128, bm = blockIdx.y;
    int b = bm >> 3, m = bm & 7;
    int dq = tid & 15, lq = tid >> 4;  // d = dq+16i (4), l = lq+16j (8)
    float acc[4][8] = {};
    for (int kc = 0; kc < 8; ++kc){
        int kb = kc*32;
        for (int i = tid; i < 2048; i += 256){
            int dd = i >> 5, kk = i & 31;
            Pt[kk*65 + dd] = g_P[((size_t)bm*DH + dd)*KH + kb + kk];
        }
        for (int i = tid; i < 4096; i += 256){
            int l = i >> 5, kk = i & 31;
            Wt[kk*129 + l] = g_W2[((size_t)bm*LL + l0 + l)*KH + kb + kk];
        }
        __syncthreads();
        #pragma unroll 4
        for (int kk = 0; kk < 32; ++kk){
            float a4[4], w8[8];
            #pragma unroll
            for (int i = 0; i < 4; ++i) a4[i] = Pt[kk*65 + dq + 16*i];
            #pragma unroll
            for (int j = 0; j < 8; ++j) w8[j] = Wt[kk*129 + lq + 16*j];
            #pragma unroll
            for (int i = 0; i < 4; ++i)
                #pragma unroll
                for (int j = 0; j < 8; ++j) acc[i][j] += a4[i]*w8[j];
        }
        __syncthreads();
    }
    #pragma unroll
    for (int j = 0; j < 8; ++j){
        size_t base = ((size_t)b*LL + l0 + lq + 16*j)*DDIM + m*64;
        #pragma unroll
        for (int i = 0; i < 4; ++i)
            g_pre[base + dq + 16*i] = acc[i][j];
    }
}

// ---------------- block reduce (128 threads) ---------------------------------
__device__ __forceinline__ float2 blockReduce2_128(float a, float b){
    __shared__ float sha[4], shb[4];
    #pragma unroll
    for (int o = 16; o > 0; o >>= 1){
        a += __shfl_down_sync(0xffffffffu, a, o);
        b += __shfl_down_sync(0xffffffffu, b, o);
    }
    int w = threadIdx.x >> 5;
    if ((threadIdx.x & 31) == 0){ sha[w] = a; shb[w] = b; }
    __syncthreads();
    float ra = sha[0]+sha[1]+sha[2]+sha[3];
    float rb = shb[0]+shb[1]+shb[2]+shb[3];
    __syncthreads();
    return make_float2(ra, rb);
}

// ---------------- kernel 4: mix = LN(pre); c1 = LN(mix) ----------------------
__global__ void k_ln_double(const float* __restrict__ g1, const float* __restrict__ b1,
                            const float* __restrict__ g2, const float* __restrict__ b2){
    int row = blockIdx.x, tid = threadIdx.x;
    const float4* src = (const float4*)(g_pre + (size_t)row*DDIM);
    float4 v = src[tid];
    float s  = v.x+v.y+v.z+v.w;
    float ss = v.x*v.x+v.y*v.y+v.z*v.z+v.w*v.w;
    float2 r = blockReduce2_128(s, ss);
    float mean = r.x*(1.0f/DDIM);
    float var  = r.y*(1.0f/DDIM) - mean*mean;
    float rs = rsqrtf(var + 1e-5f);
    float4 gg = ((const float4*)g1)[tid], bb = ((const float4*)b1)[tid];
    float4 mx;
    mx.x = (v.x-mean)*rs*gg.x + bb.x;
    mx.y = (v.y-mean)*rs*gg.y + bb.y;
    mx.z = (v.z-mean)*rs*gg.z + bb.z;
    mx.w = (v.w-mean)*rs*gg.w + bb.w;
    ((float4*)(g_mix + (size_t)row*DDIM))[tid] = mx;

    s  = mx.x+mx.y+mx.z+mx.w;
    ss = mx.x*mx.x+mx.y*mx.y+mx.z*mx.z+mx.w*mx.w;
    r = blockReduce2_128(s, ss);
    mean = r.x*(1.0f/DDIM);
    var  = r.y*(1.0f/DDIM) - mean*mean;
    rs = rsqrtf(var + 1e-5f);
    float4 g4 = ((const float4*)g2)[tid], b4 = ((const float4*)b2)[tid];
    float4 c;
    c.x = (mx.x-mean)*rs*g4.x + b4.x;
    c.y = (mx.y-mean)*rs*g4.y + b4.y;
    c.z = (mx.z-mean)*rs*g4.z + b4.z;
    c.w = (mx.w-mean)*rs*g4.w + b4.w;
    ((float4*)(g_c1 + (size_t)row*DDIM))[tid] = c;
}

// ---------------- kernel 5: generic C = A@W^T + bias (+res) ------------------
// grid (N/128, Mrows/128), 256 thr, 128x128x16 tile, 8x8/thread
__global__ void k_gemm(const float* __restrict__ A, const float* __restrict__ W,
                       const float* __restrict__ bias, const float* __restrict__ res,
                       float* __restrict__ C, int N, int K){
    __shared__ float As[16*129];
    __shared__ float Bs[16*129];
    int tid = threadIdx.x;
    int n0 = blockIdx.x*128, r0 = blockIdx.y*128;
    int mq = tid >> 4, nq = tid & 15;  // m = mq+16i, n = nq+16j
    float acc[8][8] = {};
    for (int k0 = 0; k0 < K; k0 += 16){
        for (int i = tid; i < 2048; i += 256){
            int rr = i >> 4, c = i & 15;
            As[c*129 + rr] = A[(size_t)(r0 + rr)*K + k0 + c];
        }
        for (int i = tid; i < 2048; i += 256){
            int n = i >> 4, c = i & 15;
            Bs[c*129 + n] = W[(size_t)(n0 + n)*K + k0 + c];
        }
        __syncthreads();
        #pragma unroll
        for (int c = 0; c < 16; ++c){
            float av[8], bv[8];
            #pragma unroll
            for (int i = 0; i < 8; ++i) av[i] = As[c*129 + mq + 16*i];
            #pragma unroll
            for (int j = 0; j < 8; ++j) bv[j] = Bs[c*129 + nq + 16*j];
            #pragma unroll
            for (int i = 0; i < 8; ++i)
                #pragma unroll
                for (int j = 0; j < 8; ++j) acc[i][j] += av[i]*bv[j];
        }
        __syncthreads();
    }
    #pragma unroll
    for (int i = 0; i < 8; ++i){
        int rr = r0 + mq + 16*i;
        #pragma unroll
        for (int j = 0; j < 8; ++j){
            int n = n0 + nq + 16*j;
            float v = acc[i][j] + bias[n];
            if (res) v += res[(size_t)rr*N + n];
            C[(size_t)rr*N + n] = v;
        }
    }
}

// ---------------- kernel 6: GLU ---------------------------------------------
__global__ void k_glu(){
    int idx = blockIdx.x*blockDim.x + threadIdx.x;
    if (idx >= BB*LL*DDIM) return;
    int e = idx & (DDIM-1);
    size_t row = (size_t)(idx >> 9);
    float a = g_y[row*(2*DDIM) + e];
    float s = g_y[row*(2*DDIM) + DDIM + e];
    g_glu[idx] = a / (1.0f + expf(-s));
}

// ---------------- kernel 7: depthwise conv KS=31 -----------------------------
// grid (D/128=4, L/32=64, B), 128 thr
__global__ void k_dw(const float* __restrict__ dww, const float* __restrict__ dwb){
    __shared__ float tile[62*128];
    __shared__ float dws[128*31];
    int tid = threadIdx.x;
    int d0 = blockIdx.x*128, l0 = blockIdx.y*32, b = blockIdx.z;
    int d = d0 + tid;
    for (int r = 0; r < 62; ++r){
        int l = l0 - 15 + r;
        tile[r*128 + tid] = (l >= 0 && l < LL) ? g_glu[(size_t)(b*LL + l)*DDIM + d] : 0.0f;
    }
    for (int i = tid; i < 128*31; i += 128) dws[i] = dww[d0*31 + i];
    __syncthreads();
    float bias = dwb[d];
    for (int lo = 0; lo < 32; ++lo){
        float acc = bias;
        #pragma unroll
        for (int k = 0; k < 31; ++k)
            acc += tile[(lo + k)*128 + tid] * dws[tid*31 + k];
        g_cv[(size_t)(b*LL + l0 + lo)*DDIM + d] = acc;
    }
}

// ---------------- kernel 8: c2 = gelu(LN(conv)) ------------------------------
__global__ void k_lngelu(const float* __restrict__ g1, const float* __restrict__ b1){
    int row = blockIdx.x, tid = threadIdx.x;
    const float4* src = (const float4*)(g_cv + (size_t)row*DDIM);
    float4 v = src[tid];
    float s  = v.x+v.y+v.z+v.w;
    float ss = v.x*v.x+v.y*v.y+v.z*v.z+v.w*v.w;
    float2 r = blockReduce2_128(s, ss);
    float mean = r.x*(1.0f/DDIM);
    float var  = r.y*(1.0f/DDIM) - mean*mean;
    float rs = rsqrtf(var + 1e-5f);
    float4 gg = ((const float4*)g1)[tid], bb = ((const float4*)b1)[tid];
    float4 o;
    o.x = gelu_f((v.x-mean)*rs*gg.x + bb.x);
    o.y = gelu_f((v.y-mean)*rs*gg.y + bb.y);
    o.z = gelu_f((v.z-mean)*rs*gg.z + bb.z);
    o.w = gelu_f((v.w-mean)*rs*gg.w + bb.w);
    ((float4*)(g_c2 + (size_t)row*DDIM))[tid] = o;
}

// ---------------- launch -----------------------------------------------------
extern "C" void kernel_launch(void* const* d_in, const int* in_sizes, int n_in,
                              void* d_out, int out_size){
    const float* x         = (const float*)d_in[0];
    const float* w1_fc1_w  = (const float*)d_in[1];
    const float* w1_fc1_b  = (const float*)d_in[2];
    const float* w1_fc2_w  = (const float*)d_in[3];
    const float* w1_fc2_b  = (const float*)d_in[4];
    const float* w2_fc1_w  = (const float*)d_in[5];
    const float* w2_fc1_b  = (const float*)d_in[6];
    const float* w2_fc2_w  = (const float*)d_in[7];
    const float* w2_fc2_b  = (const float*)d_in[8];
    const float* ln_mix_g  = (const float*)d_in[9];
    const float* ln_mix_b  = (const float*)d_in[10];
    const float* conv_ln1_g= (const float*)d_in[11];
    const float* conv_ln1_b= (const float*)d_in[12];
    const float* bneck_w   = (const float*)d_in[13];
    const float* bneck_b   = (const float*)d_in[14];
    const float* dw_w      = (const float*)d_in[15];
    const float* dw_b      = (const float*)d_in[16];
    const float* conv_ln2_g= (const float*)d_in[17];
    const float* conv_ln2_b= (const float*)d_in[18];
    const float* lin_w     = (const float*)d_in[19];
    const float* lin_b     = (const float*)d_in[20];

    void *pc1, *py, *pc2, *pmix;
    cudaGetSymbolAddress(&pc1,  g_c1);
    cudaGetSymbolAddress(&py,   g_y);
    cudaGetSymbolAddress(&pc2,  g_c2);
    cudaGetSymbolAddress(&pmix, g_mix);

    cudaFuncSetAttribute(k_pmlp, cudaFuncAttributeMaxDynamicSharedMemorySize,
                         PMLP_SMEM_FLOATS*sizeof(float));

    k_hyp<<<(BB*LL*DDIM + 255)/256, 256>>>(x);

    k_pmlp<<<dim3(LL/64, MMH, BB*2), 256, PMLP_SMEM_FLOATS*sizeof(float)>>>(
        w1_fc1_w, w1_fc1_b, w1_fc2_w, w1_fc2_b,
        w2_fc1_w, w2_fc1_b, w2_fc2_w, w2_fc2_b);

    k_gemmA<<<dim3(KH/128, NBM), 256>>>(x);
    k_gemmB<<<dim3(LL/128, NBM), 256>>>();

    k_ln_double<<<BB*LL, 128>>>(ln_mix_g, ln_mix_b, conv_ln1_g, conv_ln1_b);

    // bneck: [16384,512] @ [1024,512]^T -> g_y
    k_gemm<<<dim3((2*DDIM)/128, (BB*LL)/128), 256>>>(
        (const float*)pc1, bneck_w, bneck_b, nullptr, (float*)py, 2*DDIM, DDIM);

    k_glu<<<(BB*LL*DDIM + 255)/256, 256>>>();

    k_dw<<<dim3(DDIM/128, LL/32, BB), 128>>>(dw_w, dw_b);

    k_lngelu<<<BB*LL, 128>>>(conv_ln2_g, conv_ln2_b);

    // lin + residual(mix): [16384,512] @ [512,512]^T + lin_b + mix -> d_out
    k_gemm<<<dim3(DDIM/128, (BB*LL)/128), 256>>>(
        (const float*)pc2, lin_w, lin_b, (const float*)pmix, (float*)d_out, DDIM, DDIM);
}

// round 3
// speedup vs baseline: 1.4709x; 1.4709x over previous
#include <cuda_runtime.h>
#include <cstdint>
#include <math.h>

#define BB  8
#define LL  2048
#define DDIM 512
#define MMH 8
#define DH  64
#define KH  256
#define NBM (BB*MMH)     // 64

// ---------------- scratch (static __device__ globals; no allocation) ----------
__device__ float g_hyp[BB*LL*DDIM];                 // x + PE
__device__ float g_W1 [NBM*LL*KH];                  // [bm][l][k]
__device__ float g_W2 [NBM*LL*KH];
__device__ float g_P  [NBM*DH*KH];                  // gelu(xt @ W1) [bm][d][k]
__device__ float g_pre[BB*LL*DDIM];                 // pre-LN mix
__device__ float g_mix[BB*LL*DDIM];
__device__ float g_c1 [BB*LL*DDIM];                 // LN(mix) w/ conv_ln1
__device__ float g_y  [BB*LL*2*DDIM];               // bneck out
__device__ float g_glu[BB*LL*DDIM];
__device__ float g_cv [BB*LL*DDIM];                 // depthwise conv out
__device__ float g_c2 [BB*LL*DDIM];                 // gelu(LN(conv))

__device__ __forceinline__ float gelu_f(float v){
    return 0.5f*v*(1.0f + erff(v*0.70710678118654752f));
}

__device__ __forceinline__ unsigned f2tf32(float f){
    unsigned r;
    asm("cvt.rna.tf32.f32 %0, %1;" : "=r"(r) : "f"(f));
    return r;
}

__device__ __forceinline__ void mma_tf32(float c[4], const unsigned a[4], const unsigned b[2]){
    asm volatile(
        "mma.sync.aligned.m16n8k8.row.col.f32.tf32.tf32.f32 "
        "{%0,%1,%2,%3}, {%4,%5,%6,%7}, {%8,%9}, {%0,%1,%2,%3};\n"
        : "+f"(c[0]), "+f"(c[1]), "+f"(c[2]), "+f"(c[3])
        : "r"(a[0]), "r"(a[1]), "r"(a[2]), "r"(a[3]), "r"(b[0]), "r"(b[1]));
}

// ---------------- kernel 0: hyp = x + sinusoidal PE -------------------------
__global__ void k_hyp(const float* __restrict__ x){
    int idx = blockIdx.x*blockDim.x + threadIdx.x;
    if (idx >= BB*LL*DDIM) return;
    int d = idx & (DDIM-1);
    int l = (idx >> 9) & (LL-1);
    int j2 = d & ~1;
    float den = expf((float)j2 * (-9.210340371976184f/(float)DDIM));
    float ang = (float)l * den;
    float pe = (d & 1) ? cosf(ang) : sinf(ang);
    g_hyp[idx] = x[idx] + pe;
}

// ---------------- kernel 1: per-head hyper-MLP (produces W1 or W2) ----------
// stage1 FFMA (K=64 small), stage2 tf32 mma (fc2: 64x256 @ K=64)
#define PMLP_SMEM_FLOATS (4096 + 64*257 + 64 + 256 + 64*65 + 64*65)
__global__ void k_pmlp(const float* __restrict__ f1w_a, const float* __restrict__ f1b_a,
                       const float* __restrict__ f2w_a, const float* __restrict__ f2b_a,
                       const float* __restrict__ f1w_b, const float* __restrict__ f1b_b,
                       const float* __restrict__ f2w_b, const float* __restrict__ f2b_b){
    extern __shared__ float sm[];
    float*    fc1s = sm;                            // [h][f] 64x64
    unsigned* fc2t = (unsigned*)(fc1s + 4096);      // [f][k] 64x257 (tf32 bits)
    float*    b1s  = (float*)(fc2t + 64*257);       // 64
    float*    b2s  = b1s + 64;                      // 256
    float*    Xs   = b2s + 256;                     // [l][f] 64x65
    unsigned* Ht   = (unsigned*)(Xs + 64*65);       // [h][l] 64x65 (tf32 bits)

    int tid = threadIdx.x;
    int lane = tid & 31, w = tid >> 5;
    int g = lane >> 2, tg = lane & 3;
    int l0 = blockIdx.x*64, m = blockIdx.y;
    int b = blockIdx.z >> 1, which = blockIdx.z & 1;
    const float* f1w = which ? f1w_b : f1w_a;
    const float* f1b = which ? f1b_b : f1b_a;
    const float* f2w = which ? f2w_b : f2w_a;
    const float* f2b = which ? f2b_b : f2b_a;

    for (int i = tid; i < 4096; i += 256) fc1s[i] = f1w[m*4096 + i];
    for (int i = tid; i < 16384; i += 256){
        int k = i >> 6, f = i & 63;
        fc2t[f*257 + k] = f2tf32(f2w[m*16384 + i]);
    }
    if (tid < 64)  b1s[tid] = f1b[m*64 + tid];
    b2s[tid] = f2b[m*256 + tid];
    for (int i = tid; i < 4096; i += 256){
        int l = i >> 6, f = i & 63;
        Xs[l*65 + f] = g_hyp[(size_t)(b*LL + l0 + l)*DDIM + m*64 + f];
    }
    __syncthreads();

    // stage 1 (FFMA): Ht[h][l] = tf32(gelu(sum_f Xs[l][f]*fc1s[h][f] + b1[h]))
    {
        int lq = tid & 15, hq = tid >> 4;
        float acc[4][4] = {};
        for (int f = 0; f < 64; ++f){
            float xv[4], wv[4];
            #pragma unroll
            for (int j = 0; j < 4; ++j) xv[j] = Xs[(lq + 16*j)*65 + f];
            #pragma unroll
            for (int i = 0; i < 4; ++i) wv[i] = fc1s[(hq + 16*i)*64 + f];
            #pragma unroll
            for (int i = 0; i < 4; ++i)
                #pragma unroll
                for (int j = 0; j < 4; ++j) acc[i][j] += wv[i]*xv[j];
        }
        #pragma unroll
        for (int i = 0; i < 4; ++i){
            float bb = b1s[hq + 16*i];
            #pragma unroll
            for (int j = 0; j < 4; ++j)
                Ht[(hq + 16*i)*65 + (lq + 16*j)] = f2tf32(gelu_f(acc[i][j] + bb));
        }
    }
    __syncthreads();

    // stage 2 (mma): OUT[l][k] = sum_h Ht^T[l][h] * fc2t[h][k] + b2[k]
    // 8 warps: wm (l) in 0..1 -> 32 rows; wn (k) in 0..3 -> 64 cols; frags 2x8
    {
        int wm = w >> 2, wn = w & 3;
        int m0 = wm*32, n0w = wn*64;
        float c[2][8][4] = {};
        #pragma unroll
        for (int ks = 0; ks < 8; ++ks){
            int kb = ks*8;
            unsigned a[2][4];
            #pragma unroll
            for (int i = 0; i < 2; ++i){
                int mm = m0 + i*16 + g;
                a[i][0] = Ht[(kb + tg    )*65 + mm    ];
                a[i][1] = Ht[(kb + tg    )*65 + mm + 8];
                a[i][2] = Ht[(kb + tg + 4)*65 + mm    ];
                a[i][3] = Ht[(kb + tg + 4)*65 + mm + 8];
            }
            #pragma unroll
            for (int j = 0; j < 8; ++j){
                unsigned bfr[2];
                bfr[0] = fc2t[(kb + tg    )*257 + n0w + j*8 + g];
                bfr[1] = fc2t[(kb + tg + 4)*257 + n0w + j*8 + g];
                mma_tf32(c[0][j], a[0], bfr);
                mma_tf32(c[1][j], a[1], bfr);
            }
        }
        float* Wout = which ? g_W2 : g_W1;
        int bm = b*MMH + m;
        #pragma unroll
        for (int i = 0; i < 2; ++i){
            int row0 = m0 + i*16 + g;
            size_t base0 = ((size_t)bm*LL + (l0 + row0    ))*KH;
            size_t base1 = ((size_t)bm*LL + (l0 + row0 + 8))*KH;
            #pragma unroll
            for (int j = 0; j < 8; ++j){
                int col = n0w + j*8 + 2*tg;
                Wout[base0 + col    ] = c[i][j][0] + b2s[col    ];
                Wout[base0 + col + 1] = c[i][j][1] + b2s[col + 1];
                Wout[base1 + col    ] = c[i][j][2] + b2s[col    ];
                Wout[base1 + col + 1] = c[i][j][3] + b2s[col + 1];
            }
        }
    }
}

// ---------------- kernel 2: P[bm] = gelu(X^T @ W1)  (mma) --------------------
// M=64(d), N=256(k), K=2048(l). block tile 64x64x32, 8 warps (2x4), warp 32x16
__global__ void k_mixA(const float* __restrict__ x){
    __shared__ unsigned As[64*33];   // [d][l]
    __shared__ unsigned Bs[32*68];   // [l][k]
    int tid = threadIdx.x;
    int lane = tid & 31, w = tid >> 5;
    int g = lane >> 2, tg = lane & 3;
    int wm = w >> 2, wn = w & 3;
    int n0 = blockIdx.x*64;
    int bm = blockIdx.y, b = bm >> 3, mh = bm & 7;
    int l_lo = tid >> 4, q4 = (tid & 15)*4;
    float c[2][2][4] = {};
    for (int k0 = 0; k0 < LL; k0 += 32){
        #pragma unroll
        for (int li = 0; li < 32; li += 16){
            int l = l_lo + li;
            float4 v = *(const float4*)&x[(size_t)(b*LL + k0 + l)*DDIM + mh*64 + q4];
            As[(q4    )*33 + l] = f2tf32(v.x);
            As[(q4 + 1)*33 + l] = f2tf32(v.y);
            As[(q4 + 2)*33 + l] = f2tf32(v.z);
            As[(q4 + 3)*33 + l] = f2tf32(v.w);
            float4 wv = *(const float4*)&g_W1[((size_t)bm*LL + k0 + l)*KH + n0 + q4];
            uint4 u;
            u.x = f2tf32(wv.x); u.y = f2tf32(wv.y); u.z = f2tf32(wv.z); u.w = f2tf32(wv.w);
            *(uint4*)&Bs[l*68 + q4] = u;
        }
        __syncthreads();
        #pragma unroll
        for (int ks = 0; ks < 4; ++ks){
            int kb = ks*8;
            unsigned a[2][4];
            #pragma unroll
            for (int i = 0; i < 2; ++i){
                int mm = wm*32 + i*16 + g;
                a[i][0] = As[(mm    )*33 + kb + tg    ];
                a[i][1] = As[(mm + 8)*33 + kb + tg    ];
                a[i][2] = As[(mm    )*33 + kb + tg + 4];
                a[i][3] = As[(mm + 8)*33 + kb + tg + 4];
            }
            #pragma unroll
            for (int j = 0; j < 2; ++j){
                unsigned bfr[2];
                int nn = wn*16 + j*8 + g;
                bfr[0] = Bs[(kb + tg    )*68 + nn];
                bfr[1] = Bs[(kb + tg + 4)*68 + nn];
                mma_tf32(c[0][j], a[0], bfr);
                mma_tf32(c[1][j], a[1], bfr);
            }
        }
        __syncthreads();
    }
    #pragma unroll
    for (int i = 0; i < 2; ++i){
        int row0 = wm*32 + i*16 + g;
        size_t base0 = ((size_t)bm*DH + row0    )*KH + n0;
        size_t base1 = ((size_t)bm*DH + row0 + 8)*KH + n0;
        #pragma unroll
        for (int j = 0; j < 2; ++j){
            int col = wn*16 + j*8 + 2*tg;
            g_P[base0 + col    ] = gelu_f(c[i][j][0]);
            g_P[base0 + col + 1] = gelu_f(c[i][j][1]);
            g_P[base1 + col    ] = gelu_f(c[i][j][2]);
            g_P[base1 + col + 1] = gelu_f(c[i][j][3]);
        }
    }
}

// ---------------- kernel 3: pre = P @ W2^T  (mma, transposed store) ----------
// M=64(d), N=2048(l), K=256. block tile 64x128x32, 8 warps (2x4), warp 32x32
__global__ void k_mixB(){
    __shared__ __align__(16) unsigned char smraw[128*68*4];
    unsigned* As = (unsigned*)smraw;        // [d][k] 64x33
    unsigned* Bs = As + 64*33;              // [l][k] 128x33
    float*    Cs = (float*)smraw;           // [l][d] 128x68 (reused)
    int tid = threadIdx.x;
    int lane = tid & 31, w = tid >> 5;
    int g = lane >> 2, tg = lane & 3;
    int wm = w >> 2, wn = w & 3;
    int l0 = blockIdx.x*128, bm = blockIdx.y;
    int b = bm >> 3, mh = bm & 7;
    int arow = tid >> 3, akq = (tid & 7)*4;
    float c[2][4][4] = {};
    for (int k0 = 0; k0 < KH; k0 += 32){
        #pragma unroll
        for (int i = 0; i < 2; ++i){
            int r = arow + 32*i;
            float4 v = *(const float4*)&g_P[((size_t)bm*DH + r)*KH + k0 + akq];
            unsigned* dst = &As[r*33 + akq];
            dst[0]=f2tf32(v.x); dst[1]=f2tf32(v.y); dst[2]=f2tf32(v.z); dst[3]=f2tf32(v.w);
        }
        #pragma unroll
        for (int i = 0; i < 4; ++i){
            int r = arow + 32*i;
            float4 v = *(const float4*)&g_W2[((size_t)bm*LL + l0 + r)*KH + k0 + akq];
            unsigned* dst = &Bs[r*33 + akq];
            dst[0]=f2tf32(v.x); dst[1]=f2tf32(v.y); dst[2]=f2tf32(v.z); dst[3]=f2tf32(v.w);
        }
        __syncthreads();
        #pragma unroll
        for (int ks = 0; ks < 4; ++ks){
            int kb = ks*8;
            unsigned a[2][4];
            #pragma unroll
            for (int i = 0; i < 2; ++i){
                int mm = wm*32 + i*16 + g;
                a[i][0] = As[(mm    )*33 + kb + tg    ];
                a[i][1] = As[(mm + 8)*33 + kb + tg    ];
                a[i][2] = As[(mm    )*33 + kb + tg + 4];
                a[i][3] = As[(mm + 8)*33 + kb + tg + 4];
            }
            #pragma unroll
            for (int j = 0; j < 4; ++j){
                unsigned bfr[2];
                int nn = wn*32 + j*8 + g;
                bfr[0] = Bs[nn*33 + kb + tg    ];
                bfr[1] = Bs[nn*33 + kb + tg + 4];
                mma_tf32(c[0][j], a[0], bfr);
                mma_tf32(c[1][j], a[1], bfr);
            }
        }
        __syncthreads();
    }
    // stage into Cs[l][d] for coalesced [l][d] global writes
    #pragma unroll
    for (int i = 0; i < 2; ++i){
        int row0 = wm*32 + i*16 + g;
        #pragma unroll
        for (int j = 0; j < 4; ++j){
            int col = wn*32 + j*8 + 2*tg;
            Cs[(col    )*68 + row0    ] = c[i][j][0];
            Cs[(col + 1)*68 + row0    ] = c[i][j][1];
            Cs[(col    )*68 + row0 + 8] = c[i][j][2];
            Cs[(col + 1)*68 + row0 + 8] = c[i][j][3];
        }
    }
    __syncthreads();
    #pragma unroll
    for (int r = 0; r < 8; ++r){
        int s = tid + r*256;
        int l = s >> 4, d4 = (s & 15)*4;
        float4 v;
        v.x = Cs[l*68 + d4]; v.y = Cs[l*68 + d4 + 1];
        v.z = Cs[l*68 + d4 + 2]; v.w = Cs[l*68 + d4 + 3];
        *(float4*)&g_pre[((size_t)(b*LL + l0 + l))*DDIM + mh*64 + d4] = v;
    }
}

// ---------------- block reduce (128 threads) ---------------------------------
__device__ __forceinline__ float2 blockReduce2_128(float a, float b){
    __shared__ float sha[4], shb[4];
    #pragma unroll
    for (int o = 16; o > 0; o >>= 1){
        a += __shfl_down_sync(0xffffffffu, a, o);
        b += __shfl_down_sync(0xffffffffu, b, o);
    }
    int w = threadIdx.x >> 5;
    if ((threadIdx.x & 31) == 0){ sha[w] = a; shb[w] = b; }
    __syncthreads();
    float ra = sha[0]+sha[1]+sha[2]+sha[3];
    float rb = shb[0]+shb[1]+shb[2]+shb[3];
    __syncthreads();
    return make_float2(ra, rb);
}

// ---------------- kernel 4: mix = LN(pre); c1 = LN(mix) ----------------------
__global__ void k_ln_double(const float* __restrict__ g1, const float* __restrict__ b1,
                            const float* __restrict__ g2, const float* __restrict__ b2){
    int row = blockIdx.x, tid = threadIdx.x;
    const float4* src = (const float4*)(g_pre + (size_t)row*DDIM);
    float4 v = src[tid];
    float s  = v.x+v.y+v.z+v.w;
    float ss = v.x*v.x+v.y*v.y+v.z*v.z+v.w*v.w;
    float2 r = blockReduce2_128(s, ss);
    float mean = r.x*(1.0f/DDIM);
    float var  = r.y*(1.0f/DDIM) - mean*mean;
    float rs = rsqrtf(var + 1e-5f);
    float4 gg = ((const float4*)g1)[tid], bb = ((const float4*)b1)[tid];
    float4 mx;
    mx.x = (v.x-mean)*rs*gg.x + bb.x;
    mx.y = (v.y-mean)*rs*gg.y + bb.y;
    mx.z = (v.z-mean)*rs*gg.z + bb.z;
    mx.w = (v.w-mean)*rs*gg.w + bb.w;
    ((float4*)(g_mix + (size_t)row*DDIM))[tid] = mx;

    s  = mx.x+mx.y+mx.z+mx.w;
    ss = mx.x*mx.x+mx.y*mx.y+mx.z*mx.z+mx.w*mx.w;
    r = blockReduce2_128(s, ss);
    mean = r.x*(1.0f/DDIM);
    var  = r.y*(1.0f/DDIM) - mean*mean;
    rs = rsqrtf(var + 1e-5f);
    float4 g4 = ((const float4*)g2)[tid], b4 = ((const float4*)b2)[tid];
    float4 cc;
    cc.x = (mx.x-mean)*rs*g4.x + b4.x;
    cc.y = (mx.y-mean)*rs*g4.y + b4.y;
    cc.z = (mx.z-mean)*rs*g4.z + b4.z;
    cc.w = (mx.w-mean)*rs*g4.w + b4.w;
    ((float4*)(g_c1 + (size_t)row*DDIM))[tid] = cc;
}

// ---------------- kernel 5: generic tf32 mma GEMM  C = A@W^T + bias (+res) ---
// block 128x64x32, 8 warps (4x2), warp 32x32
__global__ void k_mma_nt(const float* __restrict__ A, const float* __restrict__ W,
                         const float* __restrict__ bias, const float* __restrict__ res,
                         float* __restrict__ C, int N, int K){
    __shared__ unsigned As[128*33];
    __shared__ unsigned Bs[64*33];
    int tid = threadIdx.x;
    int lane = tid & 31, w = tid >> 5;
    int g = lane >> 2, tg = lane & 3;
    int wm = w >> 1, wn = w & 1;
    int n0 = blockIdx.x*64, r0 = blockIdx.y*128;
    int arow = tid >> 3, akq = (tid & 7)*4;
    float c[2][4][4] = {};
    for (int k0 = 0; k0 < K; k0 += 32){
        #pragma unroll
        for (int i = 0; i < 4; ++i){
            int r = arow + 32*i;
            float4 v = *(const float4*)&A[(size_t)(r0 + r)*K + k0 + akq];
            unsigned* dst = &As[r*33 + akq];
            dst[0]=f2tf32(v.x); dst[1]=f2tf32(v.y); dst[2]=f2tf32(v.z); dst[3]=f2tf32(v.w);
        }
        #pragma unroll
        for (int i = 0; i < 2; ++i){
            int r = arow + 32*i;
            float4 v = *(const float4*)&W[(size_t)(n0 + r)*K + k0 + akq];
            unsigned* dst = &Bs[r*33 + akq];
            dst[0]=f2tf32(v.x); dst[1]=f2tf32(v.y); dst[2]=f2tf32(v.z); dst[3]=f2tf32(v.w);
        }
        __syncthreads();
        #pragma unroll
        for (int ks = 0; ks < 4; ++ks){
            int kb = ks*8;
            unsigned a[2][4];
            #pragma unroll
            for (int i = 0; i < 2; ++i){
                int mm = wm*32 + i*16 + g;
                a[i][0] = As[(mm    )*33 + kb + tg    ];
                a[i][1] = As[(mm + 8)*33 + kb + tg    ];
                a[i][2] = As[(mm    )*33 + kb + tg + 4];
                a[i][3] = As[(mm + 8)*33 + kb + tg + 4];
            }
            #pragma unroll
            for (int j = 0; j < 4; ++j){
                unsigned bfr[2];
                int nn = wn*32 + j*8 + g;
                bfr[0] = Bs[nn*33 + kb + tg    ];
                bfr[1] = Bs[nn*33 + kb + tg + 4];
                mma_tf32(c[0][j], a[0], bfr);
                mma_tf32(c[1][j], a[1], bfr);
            }
        }
        __syncthreads();
    }
    #pragma unroll
    for (int i = 0; i < 2; ++i){
        int row0 = r0 + wm*32 + i*16 + g;
        #pragma unroll
        for (int j = 0; j < 4; ++j){
            int col = n0 + wn*32 + j*8 + 2*tg;
            float v0 = c[i][j][0] + bias[col];
            float v1 = c[i][j][1] + bias[col+1];
            float v2 = c[i][j][2] + bias[col];
            float v3 = c[i][j][3] + bias[col+1];
            if (res){
                v0 += res[(size_t)(row0    )*N + col    ];
                v1 += res[(size_t)(row0    )*N + col + 1];
                v2 += res[(size_t)(row0 + 8)*N + col    ];
                v3 += res[(size_t)(row0 + 8)*N + col + 1];
            }
            C[(size_t)(row0    )*N + col    ] = v0;
            C[(size_t)(row0    )*N + col + 1] = v1;
            C[(size_t)(row0 + 8)*N + col    ] = v2;
            C[(size_t)(row0 + 8)*N + col + 1] = v3;
        }
    }
}

// ---------------- kernel 6: GLU ---------------------------------------------
__global__ void k_glu(){
    int idx = blockIdx.x*blockDim.x + threadIdx.x;
    if (idx >= BB*LL*DDIM) return;
    int e = idx & (DDIM-1);
    size_t row = (size_t)(idx >> 9);
    float a = g_y[row*(2*DDIM) + e];
    float s = g_y[row*(2*DDIM) + DDIM + e];
    g_glu[idx] = a / (1.0f + expf(-s));
}

// ---------------- kernel 7: depthwise conv KS=31 -----------------------------
__global__ void k_dw(const float* __restrict__ dww, const float* __restrict__ dwb){
    __shared__ float tile[62*128];
    __shared__ float dws[128*31];
    int tid = threadIdx.x;
    int d0 = blockIdx.x*128, l0 = blockIdx.y*32, b = blockIdx.z;
    int d = d0 + tid;
    for (int r = 0; r < 62; ++r){
        int l = l0 - 15 + r;
        tile[r*128 + tid] = (l >= 0 && l < LL) ? g_glu[(size_t)(b*LL + l)*DDIM + d] : 0.0f;
    }
    for (int i = tid; i < 128*31; i += 128) dws[i] = dww[d0*31 + i];
    __syncthreads();
    float bias = dwb[d];
    for (int lo = 0; lo < 32; ++lo){
        float acc = bias;
        #pragma unroll
        for (int k = 0; k < 31; ++k)
            acc += tile[(lo + k)*128 + tid] * dws[tid*31 + k];
        g_cv[(size_t)(b*LL + l0 + lo)*DDIM + d] = acc;
    }
}

// ---------------- kernel 8: c2 = gelu(LN(conv)) ------------------------------
__global__ void k_lngelu(const float* __restrict__ g1, const float* __restrict__ b1){
    int row = blockIdx.x, tid = threadIdx.x;
    const float4* src = (const float4*)(g_cv + (size_t)row*DDIM);
    float4 v = src[tid];
    float s  = v.x+v.y+v.z+v.w;
    float ss = v.x*v.x+v.y*v.y+v.z*v.z+v.w*v.w;
    float2 r = blockReduce2_128(s, ss);
    float mean = r.x*(1.0f/DDIM);
    float var  = r.y*(1.0f/DDIM) - mean*mean;
    float rs = rsqrtf(var + 1e-5f);
    float4 gg = ((const float4*)g1)[tid], bb = ((const float4*)b1)[tid];
    float4 o;
    o.x = gelu_f((v.x-mean)*rs*gg.x + bb.x);
    o.y = gelu_f((v.y-mean)*rs*gg.y + bb.y);
    o.z = gelu_f((v.z-mean)*rs*gg.z + bb.z);
    o.w = gelu_f((v.w-mean)*rs*gg.w + bb.w);
    ((float4*)(g_c2 + (size_t)row*DDIM))[tid] = o;
}

// ---------------- launch -----------------------------------------------------
extern "C" void kernel_launch(void* const* d_in, const int* in_sizes, int n_in,
                              void* d_out, int out_size){
    const float* x         = (const float*)d_in[0];
    const float* w1_fc1_w  = (const float*)d_in[1];
    const float* w1_fc1_b  = (const float*)d_in[2];
    const float* w1_fc2_w  = (const float*)d_in[3];
    const float* w1_fc2_b  = (const float*)d_in[4];
    const float* w2_fc1_w  = (const float*)d_in[5];
    const float* w2_fc1_b  = (const float*)d_in[6];
    const float* w2_fc2_w  = (const float*)d_in[7];
    const float* w2_fc2_b  = (const float*)d_in[8];
    const float* ln_mix_g  = (const float*)d_in[9];
    const float* ln_mix_b  = (const float*)d_in[10];
    const float* conv_ln1_g= (const float*)d_in[11];
    const float* conv_ln1_b= (const float*)d_in[12];
    const float* bneck_w   = (const float*)d_in[13];
    const float* bneck_b   = (const float*)d_in[14];
    const float* dw_w      = (const float*)d_in[15];
    const float* dw_b      = (const float*)d_in[16];
    const float* conv_ln2_g= (const float*)d_in[17];
    const float* conv_ln2_b= (const float*)d_in[18];
    const float* lin_w     = (const float*)d_in[19];
    const float* lin_b     = (const float*)d_in[20];

    void *pc1, *py, *pc2, *pmix;
    cudaGetSymbolAddress(&pc1,  g_c1);
    cudaGetSymbolAddress(&py,   g_y);
    cudaGetSymbolAddress(&pc2,  g_c2);
    cudaGetSymbolAddress(&pmix, g_mix);

    cudaFuncSetAttribute(k_pmlp, cudaFuncAttributeMaxDynamicSharedMemorySize,
                         PMLP_SMEM_FLOATS*sizeof(float));

    k_hyp<<<(BB*LL*DDIM + 255)/256, 256>>>(x);

    k_pmlp<<<dim3(LL/64, MMH, BB*2), 256, PMLP_SMEM_FLOATS*sizeof(float)>>>(
        w1_fc1_w, w1_fc1_b, w1_fc2_w, w1_fc2_b,
        w2_fc1_w, w2_fc1_b, w2_fc2_w, w2_fc2_b);

    k_mixA<<<dim3(KH/64, NBM), 256>>>(x);
    k_mixB<<<dim3(LL/128, NBM), 256>>>();

    k_ln_double<<<BB*LL, 128>>>(ln_mix_g, ln_mix_b, conv_ln1_g, conv_ln1_b);

    // bneck: [16384,512] @ [1024,512]^T -> g_y
    k_mma_nt<<<dim3((2*DDIM)/64, (BB*LL)/128), 256>>>(
        (const float*)pc1, bneck_w, bneck_b, nullptr, (float*)py, 2*DDIM, DDIM);

    k_glu<<<(BB*LL*DDIM + 255)/256, 256>>>();

    k_dw<<<dim3(DDIM/128, LL/32, BB), 128>>>(dw_w, dw_b);

    k_lngelu<<<BB*LL, 128>>>(conv_ln2_g, conv_ln2_b);

    // lin + residual(mix): [16384,512] @ [512,512]^T + lin_b + mix -> d_out
    k_mma_nt<<<dim3(DDIM/64, (BB*LL)/128), 256>>>(
        (const float*)pc2, lin_w, lin_b, (const float*)pmix, (float*)d_out, DDIM, DDIM);
}